// round 2
// baseline (speedup 1.0000x reference)
#include <cuda_runtime.h>
#include <math.h>
#include <stdint.h>

#define B_SZ   8
#define S_LEN  2048
#define HID    256
#define EMBD   256
#define VOC    100
#define BS     (B_SZ * S_LEN)
#define G3     768

typedef unsigned long long ull;

// ---------------- packed f32x2 helpers ----------------
__device__ __forceinline__ void fma2(ull& acc, ull a, ull b) {
    asm("fma.rn.f32x2 %0, %1, %2, %0;" : "+l"(acc) : "l"(a), "l"(b));
}
__device__ __forceinline__ ull mul2(ull a, ull b) {
    ull d; asm("mul.rn.f32x2 %0, %1, %2;" : "=l"(d) : "l"(a), "l"(b)); return d;
}
__device__ __forceinline__ ull pk2(float lo, float hi) {
    ull d; asm("mov.b64 %0, {%1, %2};" : "=l"(d) : "f"(lo), "f"(hi)); return d;
}
__device__ __forceinline__ float2 upk2(ull v) {
    float2 r; asm("mov.b64 {%0, %1}, %2;" : "=f"(r.x), "=f"(r.y) : "l"(v)); return r;
}
__device__ __forceinline__ float sigf_(float x) {
    return 1.0f / (1.0f + __expf(-x));
}

// ---------------- scratch ----------------
__device__ float g_xg[BS * G3];
__device__ float g_h[BS * HID];
__device__ float g_keys[BS * HID];
__device__ float g_ctx[BS * HID];
__device__ float g_comb[BS * HID];

// ---------------------------------------------------------------------------
// SGEMM: C[M,N] = A[M,K] @ W[N,K]^T + bias (+tanh). f32x2 microkernel.
// A stored duplicated in smem so a-operands are dup-pairs with zero packing.
// ---------------------------------------------------------------------------
__global__ void __launch_bounds__(256, 2)
gemm_kernel(const float* __restrict__ A, const float* __restrict__ A2, int K1,
            const int* __restrict__ idx,
            const float* __restrict__ W, const float* __restrict__ bias,
            float* __restrict__ C, int M, int N, int K, int act)
{
    __shared__ __align__(16) float As[8][256];   // duplicated: As[k][2i]=As[k][2i+1]=a_i
    __shared__ __align__(16) float Ws[8][128];

    const int bm  = blockIdx.y * 128;
    const int bn  = blockIdx.x * 128;
    const int tid = threadIdx.x;
    const int tx  = tid & 15;
    const int ty  = tid >> 4;
    const int lr  = tid >> 1;
    const int lk  = (tid & 1) << 2;

    ull acc2[8][4];
#pragma unroll
    for (int i = 0; i < 8; i++)
#pragma unroll
        for (int j = 0; j < 4; j++) acc2[i][j] = 0ull;

    int arow = bm + lr;
    if (idx) arow = idx[arow];
    const int wn = bn + lr;
    const int K2 = K - K1;

    for (int k0 = 0; k0 < K; k0 += 8) {
        const int kk = k0 + lk;
        float4 av;
        if (kk < K1) av = *(const float4*)(A  + (size_t)arow * K1 + kk);
        else         av = *(const float4*)(A2 + (size_t)arow * K2 + (kk - K1));
        *(ull*)&As[lk + 0][2 * lr] = pk2(av.x, av.x);
        *(ull*)&As[lk + 1][2 * lr] = pk2(av.y, av.y);
        *(ull*)&As[lk + 2][2 * lr] = pk2(av.z, av.z);
        *(ull*)&As[lk + 3][2 * lr] = pk2(av.w, av.w);

        float4 wv = make_float4(0.f, 0.f, 0.f, 0.f);
        if (wn < N) wv = *(const float4*)(W + (size_t)wn * K + kk);
        Ws[lk + 0][lr] = wv.x; Ws[lk + 1][lr] = wv.y;
        Ws[lk + 2][lr] = wv.z; Ws[lk + 3][lr] = wv.w;

        __syncthreads();
#pragma unroll
        for (int q = 0; q < 8; q++) {
            ulonglong2 ua0 = *(const ulonglong2*)&As[q][8 * ty];
            ulonglong2 ua1 = *(const ulonglong2*)&As[q][8 * ty + 4];
            ulonglong2 ua2 = *(const ulonglong2*)&As[q][128 + 8 * ty];
            ulonglong2 ua3 = *(const ulonglong2*)&As[q][128 + 8 * ty + 4];
            ulonglong2 ub0 = *(const ulonglong2*)&Ws[q][tx * 4];
            ulonglong2 ub1 = *(const ulonglong2*)&Ws[q][64 + tx * 4];
            ull a2[8] = {ua0.x, ua0.y, ua1.x, ua1.y, ua2.x, ua2.y, ua3.x, ua3.y};
            ull b2[4] = {ub0.x, ub0.y, ub1.x, ub1.y};
#pragma unroll
            for (int i = 0; i < 8; i++)
#pragma unroll
                for (int j = 0; j < 4; j++)
                    fma2(acc2[i][j], a2[i], b2[j]);
        }
        __syncthreads();
    }

#pragma unroll
    for (int i = 0; i < 8; i++) {
        const int r = bm + ((i < 4) ? (ty * 4 + i) : (64 + ty * 4 + i - 4));
        float accr[8];
#pragma unroll
        for (int j = 0; j < 4; j++) {
            float2 f = upk2(acc2[i][j]);
            accr[2 * j] = f.x; accr[2 * j + 1] = f.y;
        }
#pragma unroll
        for (int j = 0; j < 8; j++) {
            const int c = bn + ((j < 4) ? (tx * 4 + j) : (64 + tx * 4 + j - 4));
            if (c < N) {
                float v = accr[j] + bias[c];
                if (act) v = tanhf(v);
                C[(size_t)r * N + c] = v;
            }
        }
    }
}

// ---------------------------------------------------------------------------
// GRU scan. 8 batches x 8-CTA clusters, 384 thr/CTA, weights in registers.
// Sync per step: owners st.async h_new to all 8 CTAs (complete_tx), each CTA
// expect_tx(1024B) + parity wait on its own mbarrier (no cluster.sync).
// ---------------------------------------------------------------------------
__global__ void __cluster_dims__(8, 1, 1) __launch_bounds__(384, 1)
gru_kernel(const float* __restrict__ xg, const float* __restrict__ w_hh,
           const float* __restrict__ b_hh, float* __restrict__ all_h,
           float* __restrict__ hid_out)
{
    __shared__ __align__(16) float h_sm[2][4][72];  // rows 288B -> 16B aligned
    __shared__ float dots_sm[2][96];
    __shared__ float xg_sm[2][96];
    __shared__ __align__(8) ull mbar[1];

    unsigned rank;
    asm("mov.u32 %0, %%cluster_ctarank;" : "=r"(rank));
    const int b  = blockIdx.x >> 3;
    const int t  = threadIdx.x;
    const int d  = t >> 2;
    const int p  = t & 3;
    const int g  = d >> 5;
    const int jj = d & 31;
    const int grow = (g << 8) + ((int)rank << 5) + jj;

    // weights -> registers as f32x2 pairs
    ull w2[32];
    {
        const ulonglong2* wr = (const ulonglong2*)(w_hh + (size_t)grow * 256 + (p << 6));
#pragma unroll
        for (int i = 0; i < 16; i++) {
            ulonglong2 v = wr[i];
            w2[2 * i] = v.x; w2[2 * i + 1] = v.y;
        }
    }
    float bhr = 0.f, bhz = 0.f, bhn = 0.f;
    const int myj = ((int)rank << 5) + t;
    if (t < 32) {
        bhr = b_hh[myj]; bhz = b_hh[256 + myj]; bhn = b_hh[512 + myj];
    }
    if (t < 288) ((float*)h_sm)[t] = 0.0f;

    const uint32_t bar_l = (uint32_t)__cvta_generic_to_shared(mbar);
    if (t == 0) {
        asm volatile("mbarrier.init.shared.b64 [%0], %1;" :: "r"(bar_l), "r"(1) : "memory");
    }
    __syncthreads();
    asm volatile("fence.mbarrier_init.release.cluster;" ::: "memory");
    asm volatile("barrier.cluster.arrive.aligned;\n\t"
                 "barrier.cluster.wait.aligned;" ::: "memory");

    // remote addresses for owners
    uint32_t rdata[8], rbar[8];
    if (t < 32) {
        uint32_t lslot = (uint32_t)__cvta_generic_to_shared(&h_sm[0][myj >> 6][myj & 63]);
#pragma unroll
        for (unsigned r8 = 0; r8 < 8; r8++) {
            asm("mapa.shared::cluster.u32 %0, %1, %2;" : "=r"(rdata[r8]) : "r"(lslot), "r"(r8));
            asm("mapa.shared::cluster.u32 %0, %1, %2;" : "=r"(rbar[r8]) : "r"(bar_l), "r"(r8));
        }
    }

    const float* xgb = xg + (size_t)b * S_LEN * G3 + grow;
    float* hb = all_h + (size_t)b * S_LEN * HID;
    const uint32_t bufstride = 4u * 72u * 4u;   // 1152 B

    float xv = (p == 0) ? xgb[0] : 0.0f;

#pragma unroll 1
    for (int s = 0; s < S_LEN; s++) {
        const int cur = s & 1;
        float xvn = 0.0f;
        if (p == 0 && s < S_LEN - 1) xvn = xgb[(size_t)(s + 1) * G3];

        const ulonglong2* hp = (const ulonglong2*)(&h_sm[cur][p][0]);
        ull a0 = 0ull, a1 = 0ull;
#pragma unroll
        for (int i = 0; i < 16; i++) {
            ulonglong2 hv = hp[i];
            fma2(a0, w2[2 * i],     hv.x);
            fma2(a1, w2[2 * i + 1], hv.y);
        }
        float2 f0 = upk2(a0), f1 = upk2(a1);
        float acc = (f0.x + f0.y) + (f1.x + f1.y);
        acc += __shfl_xor_sync(0xffffffffu, acc, 1);
        acc += __shfl_xor_sync(0xffffffffu, acc, 2);
        if (p == 0) { dots_sm[cur][d] = acc; xg_sm[cur][d] = xv; }
        __syncthreads();

        if (t < 32) {
            const float hr = dots_sm[cur][t]      + bhr;
            const float hz = dots_sm[cur][32 + t] + bhz;
            const float hn = dots_sm[cur][64 + t] + bhn;
            const float r = sigf_(xg_sm[cur][t]      + hr);
            const float z = sigf_(xg_sm[cur][32 + t] + hz);
            const float a = xg_sm[cur][64 + t] + r * hn;
            const float n = 2.0f * sigf_(2.0f * a) - 1.0f;   // tanh(a)
            const float hold = h_sm[cur][myj >> 6][myj & 63];
            const float hnew = (1.0f - z) * n + z * hold;
            const uint32_t boff = (uint32_t)(cur ^ 1) * bufstride;
            const uint32_t hbits = __float_as_uint(hnew);
#pragma unroll
            for (unsigned r8 = 0; r8 < 8; r8++) {
                asm volatile(
                    "st.async.shared::cluster.mbarrier::complete_tx::bytes.b32 [%0], %1, [%2];"
                    :: "r"(rdata[r8] + boff), "r"(hbits), "r"(rbar[r8]) : "memory");
            }
            hb[(size_t)s * HID + myj] = hnew;
            if (s == S_LEN - 1) hid_out[b * HID + myj] = hnew;
        }
        if (t == 0) {
            asm volatile(
                "mbarrier.arrive.expect_tx.release.cluster.shared::cta.b64 _, [%0], %1;"
                :: "r"(bar_l), "r"(1024) : "memory");
        }
        {
            const uint32_t par = (uint32_t)(s & 1);
            asm volatile(
                "{\n\t.reg .pred P;\n\t"
                "WL_%=:\n\t"
                "mbarrier.try_wait.parity.acquire.cluster.shared::cta.b64 P, [%0], %1, 0x989680;\n\t"
                "@P bra.uni WD_%=;\n\t"
                "bra.uni WL_%=;\n\t"
                "WD_%=:\n\t}"
                :: "r"(bar_l), "r"(par) : "memory");
        }
        xv = xvn;
    }
}

// ---------------------------------------------------------------------------
// Causal flash attention, fp32 with f32x2 FMAs. Row-major smem tiles.
// ---------------------------------------------------------------------------
#define ATTN_SMEM_FLOATS (3 * 64 * 260 + 64 * 68 + 192)
#define ATTN_SMEM_BYTES  (ATTN_SMEM_FLOATS * 4)

__global__ void __launch_bounds__(256, 1)
attn_kernel(const float* __restrict__ h, const float* __restrict__ keys,
            float* __restrict__ ctx)
{
    extern __shared__ float sm[];
    float* Qs = sm;                  // [64][260]
    float* Ks = Qs + 64 * 260;       // [64][260]
    float* Vs = Ks + 64 * 260;       // [64][260]
    float* Ss = Vs + 64 * 260;       // [64][68]
    float* rm = Ss + 64 * 68;
    float* rl = rm + 64;
    float* ra = rl + 64;

    const int qt  = 31 - (int)blockIdx.x;
    const int b   = blockIdx.y;
    const int tid = threadIdx.x;
    const int tx  = tid & 15;
    const int ty  = tid >> 4;
    const int i0  = ty * 4;
    const int j0  = tx * 4;
    const float* Hb = h    + (size_t)b * S_LEN * HID;
    const float* Kb = keys + (size_t)b * S_LEN * HID;

#pragma unroll
    for (int it = 0; it < 16; it++) {
        const int e = it * 256 + tid;
        const int r = e >> 6, c4 = (e & 63) << 2;
        *(float4*)(Qs + r * 260 + c4) =
            *(const float4*)(Hb + (size_t)(qt * 64 + r) * HID + c4);
    }
    if (tid < 64) { rm[tid] = -1e30f; rl[tid] = 0.0f; }

    ull o2[4][8];
#pragma unroll
    for (int i = 0; i < 4; i++)
#pragma unroll
        for (int q = 0; q < 8; q++) o2[i][q] = 0ull;
    __syncthreads();

    for (int kt = 0; kt <= qt; kt++) {
#pragma unroll
        for (int it = 0; it < 16; it++) {
            const int e = it * 256 + tid;
            const int r = e >> 6, c4 = (e & 63) << 2;
            *(float4*)(Ks + r * 260 + c4) =
                *(const float4*)(Kb + (size_t)(kt * 64 + r) * HID + c4);
            *(float4*)(Vs + r * 260 + c4) =
                *(const float4*)(Hb + (size_t)(kt * 64 + r) * HID + c4);
        }
        __syncthreads();

        // ---- S = Q @ K^T : acc pairs along k ----
        ull sa[4][4];
#pragma unroll
        for (int i = 0; i < 4; i++)
#pragma unroll
            for (int j = 0; j < 4; j++) sa[i][j] = 0ull;
#pragma unroll 4
        for (int k = 0; k < 256; k += 4) {
            ulonglong2 qa[4], kb[4];
#pragma unroll
            for (int i = 0; i < 4; i++)
                qa[i] = *(const ulonglong2*)(Qs + (i0 + i) * 260 + k);
#pragma unroll
            for (int j = 0; j < 4; j++)
                kb[j] = *(const ulonglong2*)(Ks + (j0 + j) * 260 + k);
#pragma unroll
            for (int i = 0; i < 4; i++)
#pragma unroll
                for (int j = 0; j < 4; j++) {
                    fma2(sa[i][j], qa[i].x, kb[j].x);
                    fma2(sa[i][j], qa[i].y, kb[j].y);
                }
        }
        const bool diag = (kt == qt);
#pragma unroll
        for (int i = 0; i < 4; i++) {
            float4 sw;
            float* swp = &sw.x;
#pragma unroll
            for (int j = 0; j < 4; j++) {
                float2 f = upk2(sa[i][j]);
                float v = f.x + f.y;
                if (diag && (j0 + j) > (i0 + i)) v = -1e30f;
                swp[j] = v;
            }
            *(float4*)(Ss + (i0 + i) * 68 + j0) = sw;
        }
        __syncthreads();

        // ---- online softmax: 4 threads per row ----
        {
            const int row = tid >> 2, qq = tid & 3;
            float* srow = Ss + row * 68 + qq * 16;
            float4 x0 = *(float4*)(srow + 0);
            float4 x1 = *(float4*)(srow + 4);
            float4 x2 = *(float4*)(srow + 8);
            float4 x3 = *(float4*)(srow + 12);
            const float mo = rm[row];
            float mx = fmaxf(fmaxf(fmaxf(x0.x, x0.y), fmaxf(x0.z, x0.w)),
                             fmaxf(fmaxf(x1.x, x1.y), fmaxf(x1.z, x1.w)));
            mx = fmaxf(mx, fmaxf(fmaxf(fmaxf(x2.x, x2.y), fmaxf(x2.z, x2.w)),
                                 fmaxf(fmaxf(x3.x, x3.y), fmaxf(x3.z, x3.w))));
            mx = fmaxf(mx, __shfl_xor_sync(0xffffffffu, mx, 1));
            mx = fmaxf(mx, __shfl_xor_sync(0xffffffffu, mx, 2));
            mx = fmaxf(mx, mo);
            float sum;
            {
                x0.x = __expf(x0.x - mx); x0.y = __expf(x0.y - mx);
                x0.z = __expf(x0.z - mx); x0.w = __expf(x0.w - mx);
                x1.x = __expf(x1.x - mx); x1.y = __expf(x1.y - mx);
                x1.z = __expf(x1.z - mx); x1.w = __expf(x1.w - mx);
                x2.x = __expf(x2.x - mx); x2.y = __expf(x2.y - mx);
                x2.z = __expf(x2.z - mx); x2.w = __expf(x2.w - mx);
                x3.x = __expf(x3.x - mx); x3.y = __expf(x3.y - mx);
                x3.z = __expf(x3.z - mx); x3.w = __expf(x3.w - mx);
                sum = (x0.x + x0.y + x0.z + x0.w) + (x1.x + x1.y + x1.z + x1.w)
                    + (x2.x + x2.y + x2.z + x2.w) + (x3.x + x3.y + x3.z + x3.w);
                *(float4*)(srow + 0)  = x0;
                *(float4*)(srow + 4)  = x1;
                *(float4*)(srow + 8)  = x2;
                *(float4*)(srow + 12) = x3;
            }
            sum += __shfl_xor_sync(0xffffffffu, sum, 1);
            sum += __shfl_xor_sync(0xffffffffu, sum, 2);
            if (qq == 0) {
                const float al = __expf(mo - mx);
                rm[row] = mx;
                rl[row] = rl[row] * al + sum;
                ra[row] = al;
            }
        }
        __syncthreads();

        // ---- rescale + O += P @ V ----
#pragma unroll
        for (int i = 0; i < 4; i++) {
            const float al = ra[i0 + i];
            const ull ald = pk2(al, al);
#pragma unroll
            for (int q = 0; q < 8; q++) o2[i][q] = mul2(o2[i][q], ald);
        }
#pragma unroll 2
        for (int j = 0; j < 64; j++) {
            ull pd[4];
#pragma unroll
            for (int i = 0; i < 4; i++) {
                const float pv = Ss[(i0 + i) * 68 + j];
                pd[i] = pk2(pv, pv);
            }
            const ulonglong2* vp = (const ulonglong2*)(Vs + j * 260 + tx * 16);
            ulonglong2 v01 = vp[0], v23 = vp[1], v45 = vp[2], v67 = vp[3];
#pragma unroll
            for (int i = 0; i < 4; i++) {
                fma2(o2[i][0], pd[i], v01.x);
                fma2(o2[i][1], pd[i], v01.y);
                fma2(o2[i][2], pd[i], v23.x);
                fma2(o2[i][3], pd[i], v23.y);
                fma2(o2[i][4], pd[i], v45.x);
                fma2(o2[i][5], pd[i], v45.y);
                fma2(o2[i][6], pd[i], v67.x);
                fma2(o2[i][7], pd[i], v67.y);
            }
        }
        __syncthreads();
    }

#pragma unroll
    for (int i = 0; i < 4; i++) {
        const float inv = 1.0f / rl[i0 + i];
        float* dst = ctx + ((size_t)b * S_LEN + qt * 64 + i0 + i) * HID + tx * 16;
#pragma unroll
        for (int q2 = 0; q2 < 4; q2++) {
            float2 lo = upk2(o2[i][2 * q2]);
            float2 hi = upk2(o2[i][2 * q2 + 1]);
            float4 o;
            o.x = lo.x * inv; o.y = lo.y * inv;
            o.z = hi.x * inv; o.w = hi.y * inv;
            *(float4*)(dst + q2 * 4) = o;
        }
    }
}

// ---------------------------------------------------------------------------
extern "C" void kernel_launch(void* const* d_in, const int* in_sizes, int n_in,
                              void* d_out, int out_size)
{
    const int*   x      = (const int*)  d_in[0];
    const float* emb    = (const float*)d_in[1];
    const float* w_ih   = (const float*)d_in[2];
    const float* w_hh   = (const float*)d_in[3];
    const float* b_ih   = (const float*)d_in[4];
    const float* b_hh   = (const float*)d_in[5];
    const float* attn_w = (const float*)d_in[6];
    const float* attn_b = (const float*)d_in[7];
    const float* comb_w = (const float*)d_in[8];
    const float* comb_b = (const float*)d_in[9];
    const float* fc_w   = (const float*)d_in[10];
    const float* fc_b   = (const float*)d_in[11];
    float* out = (float*)d_out;

    float *xg, *h, *keys, *ctx, *comb;
    cudaGetSymbolAddress((void**)&xg,   g_xg);
    cudaGetSymbolAddress((void**)&h,    g_h);
    cudaGetSymbolAddress((void**)&keys, g_keys);
    cudaGetSymbolAddress((void**)&ctx,  g_ctx);
    cudaGetSymbolAddress((void**)&comb, g_comb);

    cudaFuncSetAttribute(attn_kernel,
                         cudaFuncAttributeMaxDynamicSharedMemorySize,
                         ATTN_SMEM_BYTES);

    gemm_kernel<<<dim3(6, 128), 256>>>(emb, nullptr, EMBD, x,
                                       w_ih, b_ih, xg, BS, G3, EMBD, 0);
    gru_kernel<<<64, 384>>>(xg, w_hh, b_hh, h, out + (size_t)BS * VOC);
    gemm_kernel<<<dim3(2, 128), 256>>>(h, nullptr, HID, nullptr,
                                       attn_w, attn_b, keys, BS, HID, HID, 0);
    attn_kernel<<<dim3(32, B_SZ), 256, ATTN_SMEM_BYTES>>>(h, keys, ctx);
    gemm_kernel<<<dim3(2, 128), 256>>>(h, ctx, HID, nullptr,
                                       comb_w, comb_b, comb, BS, HID, 2 * HID, 1);
    gemm_kernel<<<dim3(1, 128), 256>>>(comb, nullptr, HID, nullptr,
                                       fc_w, fc_b, out, BS, VOC, HID, 0);
}